// round 15
// baseline (speedup 1.0000x reference)
#include <cuda_runtime.h>
#include <math.h>

#define HWTOK 50176          // 224*224
#define BATCH 8
#define NPARAM 4576

// ---- packed per-batch fp32 layout, [i][k_pad17][o] with ODD-u64 row strides
#define RSA 18
#define RS3 5
#define OFF_CW1 0                    // 3*17*18  = 918
#define OFF_CW2 918                  // 16*17*18 = 4896
#define OFF_CW3 5814                 // 16*17*5  = 1360
#define OFF_RW1 7174                 // 3*16 = 48
#define OFF_RW2 7222                 // 16*16 = 256
#define OFF_RW3 7478                 // 16*4 = 64 (o padded)
#define PACKED_PER_B 7544            // floats, mult of 4

__device__ float g_w[BATCH * NPARAM];
__device__ float g_packed[BATCH * PACKED_PER_B];

// ---------------------------------------------------------------------------
// packed f32x2 helpers
// ---------------------------------------------------------------------------
__device__ __forceinline__ unsigned long long pk2(float x, float y)
{
    unsigned long long r;
    asm("mov.b64 %0, {%1, %2};" : "=l"(r) : "f"(x), "f"(y));
    return r;
}
__device__ __forceinline__ unsigned long long ffma2(unsigned long long a,
                                                    unsigned long long b,
                                                    unsigned long long c)
{
    unsigned long long d;
    asm("fma.rn.f32x2 %0, %1, %2, %3;" : "=l"(d) : "l"(a), "l"(b), "l"(c));
    return d;
}
__device__ __forceinline__ void upk2(unsigned long long v, float& x, float& y)
{
    asm("mov.b64 {%0, %1}, %2;" : "=f"(x), "=f"(y) : "l"(v));
}

// ---------------------------------------------------------------------------
// Kernel 1: w[b][p] = features[b,:] . fc_w[p,:] + fc_b[p]
// 512 threads/block, ONE row per warp -> grid = 286 = ~2 CTAs/SM = ~31
// warps/SM (the R13 config was grid-limited to 16 warps/SM). Per-warp code
// = R3's proven single-row loop: 8 LDG.128 prefetched, low regs (no cap).
// ---------------------------------------------------------------------------
__global__ void __launch_bounds__(512)
compute_w_kernel(const float* __restrict__ features,
                 const float* __restrict__ fc_w,
                 const float* __restrict__ fc_b)
{
    __shared__ float4 sfeat[BATCH * 250];
    const float4* f4 = (const float4*)features;
    for (int idx = threadIdx.x; idx < BATCH * 250; idx += blockDim.x)
        sfeat[idx] = f4[idx];
    __syncthreads();

    int warp = (blockIdx.x * blockDim.x + threadIdx.x) >> 5;
    int lane = threadIdx.x & 31;
    if (warp >= NPARAM) return;

    const float4* row = (const float4*)(fc_w + warp * 1000);

    // 8 independent LDG.128 in flight
    float4 fw[8];
#pragma unroll
    for (int it = 0; it < 8; it++) {
        int idx = it * 32 + lane;
        fw[it] = (idx < 250) ? row[idx] : make_float4(0.f, 0.f, 0.f, 0.f);
    }

    float acc[BATCH];
#pragma unroll
    for (int b = 0; b < BATCH; b++) acc[b] = 0.0f;

#pragma unroll
    for (int it = 0; it < 8; it++) {
        int idx = it * 32 + lane;
        if (idx < 250) {
#pragma unroll
            for (int b = 0; b < BATCH; b++) {
                float4 sf = sfeat[b * 250 + idx];
                acc[b] = fmaf(fw[it].x, sf.x, acc[b]);
                acc[b] = fmaf(fw[it].y, sf.y, acc[b]);
                acc[b] = fmaf(fw[it].z, sf.z, acc[b]);
                acc[b] = fmaf(fw[it].w, sf.w, acc[b]);
            }
        }
    }
#pragma unroll
    for (int b = 0; b < BATCH; b++) {
#pragma unroll
        for (int off = 16; off; off >>= 1)
            acc[b] += __shfl_xor_sync(0xffffffffu, acc[b], off);
    }
    if (lane == 0) {
        float bb = fc_b[warp];
#pragma unroll
        for (int b = 0; b < BATCH; b++)
            g_w[b * NPARAM + warp] = acc[b] + bb;
    }
}

// ---------------------------------------------------------------------------
// Kernel 2: build fused, transposed, padded per-batch parameter block
// ---------------------------------------------------------------------------
__global__ void pack_kernel()
{
    int b = blockIdx.x;
    const float* w = g_w + b * NPARAM;
    float* pk = g_packed + b * PACKED_PER_B;

    for (int idx = threadIdx.x; idx < PACKED_PER_B; idx += blockDim.x)
        pk[idx] = 0.0f;
    __syncthreads();

    const int i0s[3]   = {0,    624,  3952};
    const int i1s[3]   = {528,  3440, 4480};
    const int i2s[3]   = {576,  3696, 4528};
    const int dis[3]   = {3, 16, 16};
    const int dos[3]   = {16, 16, 3};
    const int rss[3]   = {RSA, RSA, RS3};
    const int dopr[3]  = {16, 16, 4};
    const int cwoff[3] = {OFF_CW1, OFF_CW2, OFF_CW3};
    const int rwoff[3] = {OFF_RW1, OFF_RW2, OFF_RW3};

    for (int n = 0; n < 3; n++) {
        int nd = dis[n] * dos[n];
        int rs = rss[n];
        for (int p = threadIdx.x; p < nd; p += blockDim.x) {
            int i = p / dos[n];
            int o = p % dos[n];
            float uwv = w[i1s[n] + p];
            const float* cf = w + i0s[n] + p * 11;
            float* dst = pk + cwoff[n] + (i * 17 + 3) * rs + o;
#pragma unroll
            for (int k = 0; k < 11; k++) dst[k * rs] = cf[k] * uwv;
            pk[rwoff[n] + i * dopr[n] + o] = w[i2s[n] + p];
        }
    }
}

// ---------------------------------------------------------------------------
// Closed-form uniform cubic B-spline weights (h=0.25 grid over [-1.75,1.75)).
// ---------------------------------------------------------------------------
__device__ __forceinline__ void bweights(float v, int& j,
                                         float& w0, float& w1, float& w2, float& w3)
{
    float x4 = (v + 1.75f) * 4.0f;
    float jf = floorf(x4);
    bool inr = (x4 >= 0.0f) && (x4 < 14.0f);
    j = inr ? (int)jf : 0;
    float t  = x4 - jf;
    float u  = 1.0f - t;
    float t2 = t * t;
    float t3 = t2 * t;
    w0 = u * u * u * (1.0f / 6.0f);
    w1 = 0.5f * t3 - t2 + (2.0f / 3.0f);
    w3 = t3 * (1.0f / 6.0f);
    w2 = 1.0f - w0 - w1 - w3;
    if (!inr) { w0 = w1 = w2 = w3 = 0.0f; }
}

// silu via fast reciprocal: MUFU.RCP + FMUL instead of refined fdiv
__device__ __forceinline__ float silu_f(float v)
{
    return __fdividef(v, 1.0f + __expf(-v));
}

// ---------------------------------------------------------------------------
// Layers 1/2: DOP=16, row stride 18 floats (9 u64, conflict-free LDS.64).
// ---------------------------------------------------------------------------
template<int DI>
__device__ __forceinline__ void kan_layer16(const float* __restrict__ cw,
                                            const float* __restrict__ rw,
                                            const float* __restrict__ in,
                                            float* __restrict__ outv)
{
    unsigned long long acc[8];
#pragma unroll
    for (int p = 0; p < 8; p++) acc[p] = 0ull;

#pragma unroll
    for (int i = 0; i < DI; i++) {
        float v = in[i];
        int j; float w0, w1, w2, w3;
        bweights(v, j, w0, w1, w2, w3);
        float sl = silu_f(v);

        unsigned long long SL = pk2(sl, sl);
        unsigned long long W0 = pk2(w0, w0), W1 = pk2(w1, w1);
        unsigned long long W2 = pk2(w2, w2), W3 = pk2(w3, w3);

        const unsigned long long* rr = (const unsigned long long*)(rw + i * 16);
        const unsigned long long* r0 =
            (const unsigned long long*)(cw + (i * 17 + j) * RSA);
        const unsigned long long* r1 = r0 + (RSA / 2);
        const unsigned long long* r2 = r1 + (RSA / 2);
        const unsigned long long* r3 = r2 + (RSA / 2);

#pragma unroll
        for (int p = 0; p < 8; p++) acc[p] = ffma2(SL, rr[p], acc[p]);
#pragma unroll
        for (int p = 0; p < 8; p++) acc[p] = ffma2(W0, r0[p], acc[p]);
#pragma unroll
        for (int p = 0; p < 8; p++) acc[p] = ffma2(W1, r1[p], acc[p]);
#pragma unroll
        for (int p = 0; p < 8; p++) acc[p] = ffma2(W2, r2[p], acc[p]);
#pragma unroll
        for (int p = 0; p < 8; p++) acc[p] = ffma2(W3, r3[p], acc[p]);
    }
#pragma unroll
    for (int p = 0; p < 8; p++)
        upk2(acc[p], outv[2 * p], outv[2 * p + 1]);
}

// ---------------------------------------------------------------------------
// Layer 3: DO=3, scalar loads, row stride 5 floats (odd -> conflict-free).
// ---------------------------------------------------------------------------
__device__ __forceinline__ void kan_layer3(const float* __restrict__ cw,
                                           const float* __restrict__ rw,
                                           const float* __restrict__ in,
                                           float* __restrict__ outv)
{
    float a0 = 0.f, a1 = 0.f, a2 = 0.f;
#pragma unroll
    for (int i = 0; i < 16; i++) {
        float v = in[i];
        int j; float w0, w1, w2, w3;
        bweights(v, j, w0, w1, w2, w3);
        float sl = silu_f(v);

        const float* r = cw + (i * 17 + j) * RS3;
        const float* rwp = rw + i * 4;

        a0 += fmaf(w0, r[0], fmaf(w1, r[RS3], fmaf(w2, r[2*RS3], w3 * r[3*RS3])))
              + sl * rwp[0];
        a1 += fmaf(w0, r[1], fmaf(w1, r[RS3+1], fmaf(w2, r[2*RS3+1], w3 * r[3*RS3+1])))
              + sl * rwp[1];
        a2 += fmaf(w0, r[2], fmaf(w1, r[RS3+2], fmaf(w2, r[2*RS3+2], w3 * r[3*RS3+2])))
              + sl * rwp[2];
    }
    outv[0] = a0; outv[1] = a1; outv[2] = a2;
}

// ---------------------------------------------------------------------------
// Main kernel: one thread = one token (R13-exact; FROZEN).
// ---------------------------------------------------------------------------
__global__ void __launch_bounds__(256)
kan_main_kernel(const float* __restrict__ x, float* __restrict__ out)
{
    __shared__ __align__(16) float sp[PACKED_PER_B];
    int b = blockIdx.y;
    {
        const float4* src4 = (const float4*)(g_packed + b * PACKED_PER_B);
        float4* dst4 = (float4*)sp;
        for (int idx = threadIdx.x; idx < PACKED_PER_B / 4; idx += blockDim.x)
            dst4[idx] = src4[idx];
    }
    __syncthreads();

    int t = blockIdx.x * blockDim.x + threadIdx.x;
    const float* xb = x + b * (3 * HWTOK);

    float in1[3];
    in1[0] = xb[t];
    in1[1] = xb[HWTOK + t];
    in1[2] = xb[2 * HWTOK + t];

    float h1[16], h2[16], h3[3];
    kan_layer16<3>(sp + OFF_CW1, sp + OFF_RW1, in1, h1);
    kan_layer16<16>(sp + OFF_CW2, sp + OFF_RW2, h1, h2);
    kan_layer3(sp + OFF_CW3, sp + OFF_RW3, h2, h3);

    float* ob = out + b * (3 * HWTOK);
    ob[t]             = h3[0];
    ob[HWTOK + t]     = h3[1];
    ob[2 * HWTOK + t] = h3[2];
}

// ---------------------------------------------------------------------------
extern "C" void kernel_launch(void* const* d_in, const int* in_sizes, int n_in,
                              void* d_out, int out_size)
{
    const float* x   = (const float*)d_in[0];
    const float* ft  = (const float*)d_in[1];
    const float* fcw = (const float*)d_in[2];
    const float* fcb = (const float*)d_in[3];
    float* out = (float*)d_out;

    // 1 row per warp, 16 warps per 512-thr block -> grid = 286
    compute_w_kernel<<<(NPARAM * 32 + 511) / 512, 512>>>(ft, fcw, fcb);
    pack_kernel<<<BATCH, 256>>>();
    dim3 g(HWTOK / 256, BATCH);
    kan_main_kernel<<<g, 256>>>(x, out);
}

// round 16
// speedup vs baseline: 1.0191x; 1.0191x over previous
#include <cuda_runtime.h>
#include <math.h>

#define HWTOK 50176          // 224*224
#define BATCH 8
#define NPARAM 4576

// ---- packed per-batch fp32 layout, [i][k_pad17][o] with ODD-u64 row strides
#define RSA 18
#define RS3 5
#define OFF_CW1 0                    // 3*17*18  = 918
#define OFF_CW2 918                  // 16*17*18 = 4896
#define OFF_CW3 5814                 // 16*17*5  = 1360
#define OFF_RW1 7174                 // 3*16 = 48
#define OFF_RW2 7222                 // 16*16 = 256
#define OFF_RW3 7478                 // 16*4 = 64 (o padded)
#define PACKED_PER_B 7544            // floats, mult of 4

__device__ float g_w[BATCH * NPARAM];
__device__ __align__(16) float g_packed[BATCH * PACKED_PER_B];

// ---------------------------------------------------------------------------
// packed f32x2 helpers
// ---------------------------------------------------------------------------
__device__ __forceinline__ unsigned long long pk2(float x, float y)
{
    unsigned long long r;
    asm("mov.b64 %0, {%1, %2};" : "=l"(r) : "f"(x), "f"(y));
    return r;
}
__device__ __forceinline__ unsigned long long ffma2(unsigned long long a,
                                                    unsigned long long b,
                                                    unsigned long long c)
{
    unsigned long long d;
    asm("fma.rn.f32x2 %0, %1, %2, %3;" : "=l"(d) : "l"(a), "l"(b), "l"(c));
    return d;
}
__device__ __forceinline__ void upk2(unsigned long long v, float& x, float& y)
{
    asm("mov.b64 {%0, %1}, %2;" : "=f"(x), "=f"(y) : "l"(v));
}

// ---------------------------------------------------------------------------
// Kernel 1: w[b][p] = features[b,:] . fc_w[p,:] + fc_b[p]
// R13-exact (measured best 10.88us): 512 threads/block, 2 rows per warp,
// staged features, two 4+4 LDG.128 prefetch waves, NO reg cap (86 regs is
// good: at 1 CTA/SM registers are free and buy LDG depth).
// ---------------------------------------------------------------------------
__global__ void __launch_bounds__(512)
compute_w_kernel(const float* __restrict__ features,
                 const float* __restrict__ fc_w,
                 const float* __restrict__ fc_b)
{
    __shared__ float4 sfeat[BATCH * 250];
    const float4* f4 = (const float4*)features;
    for (int idx = threadIdx.x; idx < BATCH * 250; idx += blockDim.x)
        sfeat[idx] = f4[idx];
    __syncthreads();

    int gw   = (blockIdx.x * blockDim.x + threadIdx.x) >> 5;
    int lane = threadIdx.x & 31;
    int r0 = gw * 2;
    if (r0 >= NPARAM) return;
    int r1 = r0 + 1;

    const float4* rowA = (const float4*)(fc_w + r0 * 1000);
    const float4* rowB = (const float4*)(fc_w + r1 * 1000);

    float accA[BATCH], accB[BATCH];
#pragma unroll
    for (int b = 0; b < BATCH; b++) { accA[b] = 0.0f; accB[b] = 0.0f; }

#pragma unroll
    for (int half = 0; half < 2; half++) {
        float4 fa[4], fbv[4];
#pragma unroll
        for (int it = 0; it < 4; it++) {
            int idx = half * 128 + it * 32 + lane;
            bool ok = idx < 250;
            fa[it]  = ok ? rowA[idx] : make_float4(0.f, 0.f, 0.f, 0.f);
            fbv[it] = ok ? rowB[idx] : make_float4(0.f, 0.f, 0.f, 0.f);
        }
#pragma unroll
        for (int it = 0; it < 4; it++) {
            int idx = half * 128 + it * 32 + lane;
            if (idx < 250) {
#pragma unroll
                for (int b = 0; b < BATCH; b++) {
                    float4 sf = sfeat[b * 250 + idx];
                    accA[b] = fmaf(fa[it].x, sf.x, accA[b]);
                    accA[b] = fmaf(fa[it].y, sf.y, accA[b]);
                    accA[b] = fmaf(fa[it].z, sf.z, accA[b]);
                    accA[b] = fmaf(fa[it].w, sf.w, accA[b]);
                    accB[b] = fmaf(fbv[it].x, sf.x, accB[b]);
                    accB[b] = fmaf(fbv[it].y, sf.y, accB[b]);
                    accB[b] = fmaf(fbv[it].z, sf.z, accB[b]);
                    accB[b] = fmaf(fbv[it].w, sf.w, accB[b]);
                }
            }
        }
    }
#pragma unroll
    for (int b = 0; b < BATCH; b++) {
#pragma unroll
        for (int off = 16; off; off >>= 1) {
            accA[b] += __shfl_xor_sync(0xffffffffu, accA[b], off);
            accB[b] += __shfl_xor_sync(0xffffffffu, accB[b], off);
        }
    }
    if (lane == 0) {
        float b0 = fc_b[r0];
        float b1 = fc_b[r1];
#pragma unroll
        for (int b = 0; b < BATCH; b++) {
            g_w[b * NPARAM + r0] = accA[b] + b0;
            g_w[b * NPARAM + r1] = accB[b] + b1;
        }
    }
}

// ---------------------------------------------------------------------------
// Kernel 2: build fused, transposed, padded per-batch parameter block.
// 512 threads + float4 zero-fill (was 256 thr + scalar fill).
// ---------------------------------------------------------------------------
__global__ void __launch_bounds__(512)
pack_kernel()
{
    int b = blockIdx.x;
    const float* w = g_w + b * NPARAM;
    float* pk = g_packed + b * PACKED_PER_B;

    {
        float4* pk4 = (float4*)pk;
        float4 z = make_float4(0.f, 0.f, 0.f, 0.f);
        for (int idx = threadIdx.x; idx < PACKED_PER_B / 4; idx += blockDim.x)
            pk4[idx] = z;
    }
    __syncthreads();

    const int i0s[3]   = {0,    624,  3952};
    const int i1s[3]   = {528,  3440, 4480};
    const int i2s[3]   = {576,  3696, 4528};
    const int dis[3]   = {3, 16, 16};
    const int dos[3]   = {16, 16, 3};
    const int rss[3]   = {RSA, RSA, RS3};
    const int dopr[3]  = {16, 16, 4};
    const int cwoff[3] = {OFF_CW1, OFF_CW2, OFF_CW3};
    const int rwoff[3] = {OFF_RW1, OFF_RW2, OFF_RW3};

    for (int n = 0; n < 3; n++) {
        int nd = dis[n] * dos[n];
        int rs = rss[n];
        for (int p = threadIdx.x; p < nd; p += blockDim.x) {
            int i = p / dos[n];
            int o = p % dos[n];
            float uwv = w[i1s[n] + p];
            const float* cf = w + i0s[n] + p * 11;
            float* dst = pk + cwoff[n] + (i * 17 + 3) * rs + o;
#pragma unroll
            for (int k = 0; k < 11; k++) dst[k * rs] = cf[k] * uwv;
            pk[rwoff[n] + i * dopr[n] + o] = w[i2s[n] + p];
        }
    }
}

// ---------------------------------------------------------------------------
// Closed-form uniform cubic B-spline weights (h=0.25 grid over [-1.75,1.75)).
// ---------------------------------------------------------------------------
__device__ __forceinline__ void bweights(float v, int& j,
                                         float& w0, float& w1, float& w2, float& w3)
{
    float x4 = (v + 1.75f) * 4.0f;
    float jf = floorf(x4);
    bool inr = (x4 >= 0.0f) && (x4 < 14.0f);
    j = inr ? (int)jf : 0;
    float t  = x4 - jf;
    float u  = 1.0f - t;
    float t2 = t * t;
    float t3 = t2 * t;
    w0 = u * u * u * (1.0f / 6.0f);
    w1 = 0.5f * t3 - t2 + (2.0f / 3.0f);
    w3 = t3 * (1.0f / 6.0f);
    w2 = 1.0f - w0 - w1 - w3;
    if (!inr) { w0 = w1 = w2 = w3 = 0.0f; }
}

// silu via fast reciprocal: MUFU.RCP + FMUL instead of refined fdiv
__device__ __forceinline__ float silu_f(float v)
{
    return __fdividef(v, 1.0f + __expf(-v));
}

// ---------------------------------------------------------------------------
// Layers 1/2: DOP=16, row stride 18 floats (9 u64, conflict-free LDS.64).
// ---------------------------------------------------------------------------
template<int DI>
__device__ __forceinline__ void kan_layer16(const float* __restrict__ cw,
                                            const float* __restrict__ rw,
                                            const float* __restrict__ in,
                                            float* __restrict__ outv)
{
    unsigned long long acc[8];
#pragma unroll
    for (int p = 0; p < 8; p++) acc[p] = 0ull;

#pragma unroll
    for (int i = 0; i < DI; i++) {
        float v = in[i];
        int j; float w0, w1, w2, w3;
        bweights(v, j, w0, w1, w2, w3);
        float sl = silu_f(v);

        unsigned long long SL = pk2(sl, sl);
        unsigned long long W0 = pk2(w0, w0), W1 = pk2(w1, w1);
        unsigned long long W2 = pk2(w2, w2), W3 = pk2(w3, w3);

        const unsigned long long* rr = (const unsigned long long*)(rw + i * 16);
        const unsigned long long* r0 =
            (const unsigned long long*)(cw + (i * 17 + j) * RSA);
        const unsigned long long* r1 = r0 + (RSA / 2);
        const unsigned long long* r2 = r1 + (RSA / 2);
        const unsigned long long* r3 = r2 + (RSA / 2);

#pragma unroll
        for (int p = 0; p < 8; p++) acc[p] = ffma2(SL, rr[p], acc[p]);
#pragma unroll
        for (int p = 0; p < 8; p++) acc[p] = ffma2(W0, r0[p], acc[p]);
#pragma unroll
        for (int p = 0; p < 8; p++) acc[p] = ffma2(W1, r1[p], acc[p]);
#pragma unroll
        for (int p = 0; p < 8; p++) acc[p] = ffma2(W2, r2[p], acc[p]);
#pragma unroll
        for (int p = 0; p < 8; p++) acc[p] = ffma2(W3, r3[p], acc[p]);
    }
#pragma unroll
    for (int p = 0; p < 8; p++)
        upk2(acc[p], outv[2 * p], outv[2 * p + 1]);
}

// ---------------------------------------------------------------------------
// Layer 3: DO=3, scalar loads, row stride 5 floats (odd -> conflict-free).
// ---------------------------------------------------------------------------
__device__ __forceinline__ void kan_layer3(const float* __restrict__ cw,
                                           const float* __restrict__ rw,
                                           const float* __restrict__ in,
                                           float* __restrict__ outv)
{
    float a0 = 0.f, a1 = 0.f, a2 = 0.f;
#pragma unroll
    for (int i = 0; i < 16; i++) {
        float v = in[i];
        int j; float w0, w1, w2, w3;
        bweights(v, j, w0, w1, w2, w3);
        float sl = silu_f(v);

        const float* r = cw + (i * 17 + j) * RS3;
        const float* rwp = rw + i * 4;

        a0 += fmaf(w0, r[0], fmaf(w1, r[RS3], fmaf(w2, r[2*RS3], w3 * r[3*RS3])))
              + sl * rwp[0];
        a1 += fmaf(w0, r[1], fmaf(w1, r[RS3+1], fmaf(w2, r[2*RS3+1], w3 * r[3*RS3+1])))
              + sl * rwp[1];
        a2 += fmaf(w0, r[2], fmaf(w1, r[RS3+2], fmaf(w2, r[2*RS3+2], w3 * r[3*RS3+2])))
              + sl * rwp[2];
    }
    outv[0] = a0; outv[1] = a1; outv[2] = a2;
}

// ---------------------------------------------------------------------------
// Main kernel: one thread = one token (R13-exact; FROZEN).
// ---------------------------------------------------------------------------
__global__ void __launch_bounds__(256)
kan_main_kernel(const float* __restrict__ x, float* __restrict__ out)
{
    __shared__ __align__(16) float sp[PACKED_PER_B];
    int b = blockIdx.y;
    {
        const float4* src4 = (const float4*)(g_packed + b * PACKED_PER_B);
        float4* dst4 = (float4*)sp;
        for (int idx = threadIdx.x; idx < PACKED_PER_B / 4; idx += blockDim.x)
            dst4[idx] = src4[idx];
    }
    __syncthreads();

    int t = blockIdx.x * blockDim.x + threadIdx.x;
    const float* xb = x + b * (3 * HWTOK);

    float in1[3];
    in1[0] = xb[t];
    in1[1] = xb[HWTOK + t];
    in1[2] = xb[2 * HWTOK + t];

    float h1[16], h2[16], h3[3];
    kan_layer16<3>(sp + OFF_CW1, sp + OFF_RW1, in1, h1);
    kan_layer16<16>(sp + OFF_CW2, sp + OFF_RW2, h1, h2);
    kan_layer3(sp + OFF_CW3, sp + OFF_RW3, h2, h3);

    float* ob = out + b * (3 * HWTOK);
    ob[t]             = h3[0];
    ob[HWTOK + t]     = h3[1];
    ob[2 * HWTOK + t] = h3[2];
}

// ---------------------------------------------------------------------------
extern "C" void kernel_launch(void* const* d_in, const int* in_sizes, int n_in,
                              void* d_out, int out_size)
{
    const float* x   = (const float*)d_in[0];
    const float* ft  = (const float*)d_in[1];
    const float* fcw = (const float*)d_in[2];
    const float* fcb = (const float*)d_in[3];
    float* out = (float*)d_out;

    int warps = NPARAM / 2;   // 2 rows per warp, 16 warps per 512-thr block
    compute_w_kernel<<<(warps * 32 + 511) / 512, 512>>>(ft, fcw, fcb);
    pack_kernel<<<BATCH, 512>>>();
    dim3 g(HWTOK / 256, BATCH);
    kan_main_kernel<<<g, 256>>>(x, out);
}